// round 16
// baseline (speedup 1.0000x reference)
#include <cuda_runtime.h>
#include <cuda_bf16.h>
#include <cuda_fp16.h>
#include <math.h>
#include <stdint.h>

#define NN 100000
#define EE 800000
#define DH 128
#define DOUT 40
#define NLAYERS 16
#define ALPHA 0.1f
#define THETA 0.5f
#define BN_EPS 1e-5f
#define NN_PAD (782 * 128)

// ---------------- scratch (device globals; zero-initialized at load) ----------------
__device__ uint32_t g_x0h[(size_t)NN * 64];       // x0 as half2 pairs
__device__ uint32_t g_hh [(size_t)NN * 64];       // h  as half2 pairs
__device__ float    g_a2[(size_t)NN * DH];        // layer GEMM output (fp32)
// input GEMM (bf16 3-term) operands
__device__ uint32_t g_Ahi[(size_t)NN_PAD * 64];   // bf16x2 hi-split of x
__device__ uint32_t g_Alo[(size_t)NN_PAD * 64];
__device__ uint2    g_Bfh[4096];                   // W_in bf16 hi frags
__device__ uint2    g_Bfl[4096];                   // W_in bf16 lo frags
// layer GEMMs: pure fp16 (1 MMA per fragment)
__device__ uint32_t g_A16h[(size_t)NN_PAD * 64];   // fp16 of spmm output
__device__ uint2    g_B16h[NLAYERS * 4096];        // fp16(Wp) frags
__device__ int   g_ptr[NN + 1];
__device__ int   g_cnt[NN];
__device__ int2  g_cw[EE];                         // packed (col, w-bits)
__device__ int   g_csum[128];
__device__ float g_sum[DH], g_sq[DH];

// ---------------- helpers ----------------
__device__ __forceinline__ uint32_t smem_u32(const void* p) {
    uint32_t a;
    asm("{ .reg .u64 t; cvta.to.shared.u64 t, %1; cvt.u32.u64 %0, t; }" : "=r"(a) : "l"(p));
    return a;
}
__device__ __forceinline__ uint32_t pack_split(float a, float b, uint32_t& lo_out) {
    __nv_bfloat162 hi2 = __float22bfloat162_rn(make_float2(a, b));
    float ra = a - __bfloat162float(hi2.x);
    float rb = b - __bfloat162float(hi2.y);
    __nv_bfloat162 lo2 = __float22bfloat162_rn(make_float2(ra, rb));
    lo_out = *(uint32_t*)&lo2;
    return *(uint32_t*)&hi2;
}
__device__ __forceinline__ uint32_t pack_half2(float a, float b) {
    __half2 h = __float22half2_rn(make_float2(a, b));
    return *(uint32_t*)&h;
}
__device__ __forceinline__ float2 unpack_half2(uint32_t v) {
    return __half22float2(*(__half2*)&v);
}

#define MMA16816(D, A0, A1, A2, A3, B0, B1) \
    asm volatile("mma.sync.aligned.m16n8k16.row.col.f32.bf16.bf16.f32 " \
        "{%0,%1,%2,%3}, {%4,%5,%6,%7}, {%8,%9}, {%0,%1,%2,%3};" \
        : "+f"((D)[0]), "+f"((D)[1]), "+f"((D)[2]), "+f"((D)[3]) \
        : "r"(A0), "r"(A1), "r"(A2), "r"(A3), "r"(B0), "r"(B1))

#define MMA16816H(D, A0, A1, A2, A3, B0, B1) \
    asm volatile("mma.sync.aligned.m16n8k16.row.col.f32.f16.f16.f32 " \
        "{%0,%1,%2,%3}, {%4,%5,%6,%7}, {%8,%9}, {%0,%1,%2,%3};" \
        : "+f"((D)[0]), "+f"((D)[1]), "+f"((D)[2]), "+f"((D)[3]) \
        : "r"(A0), "r"(A1), "r"(A2), "r"(A3), "r"(B0), "r"(B1))

#define LDMATRIX_X4(R, addr) \
    asm volatile("ldmatrix.sync.aligned.m8n8.x4.shared.b16 {%0,%1,%2,%3}, [%4];" \
        : "=r"((R)[0]), "=r"((R)[1]), "=r"((R)[2]), "=r"((R)[3]) : "r"(addr))

__device__ __forceinline__ void cp16(uint32_t dst, const void* src) {
    asm volatile("cp.async.cg.shared.global [%0], [%1], 16;" :: "r"(dst), "l"(src));
}
#define CP_COMMIT() asm volatile("cp.async.commit_group;" ::: "memory")
#define CP_WAIT(n)  asm volatile("cp.async.wait_group %0;" :: "n"(n) : "memory")

// ---------------- weight prep: input GEMM (bf16 3-term, W_in) ----------------
__global__ void k_prep_bin(const float* __restrict__ W_in) {
    int i = blockIdx.x * blockDim.x + threadIdx.x;
    if (i >= 4096) return;
    int lane = i & 31;
    int nt   = (i >> 5) & 15;
    int s    = (i >> 9) & 7;
    int k0 = s * 16 + (lane & 3) * 2;
    int n  = nt * 8 + (lane >> 2);
    float v[4];
#pragma unroll
    for (int j = 0; j < 4; j++) {
        int k = k0 + (j & 1) + (j >> 1) * 8;
        v[j] = W_in[k * 128 + n];
    }
    uint32_t loA, loB;
    uint32_t hiA = pack_split(v[0], v[1], loA);
    uint32_t hiB = pack_split(v[2], v[3], loB);
    g_Bfh[i] = make_uint2(hiA, hiB);
    g_Bfl[i] = make_uint2(loA, loB);
}

// ---------------- weight prep: layers (fp16 fold + fragment pack) ----------------
__global__ void k_prep_b16(const float* __restrict__ convW) {
    int i = blockIdx.x * blockDim.x + threadIdx.x;
    if (i >= NLAYERS * 4096) return;
    int lane = i & 31;
    int nt   = (i >> 5) & 15;
    int s    = (i >> 9) & 7;
    int l    = i >> 12;
    int k0 = s * 16 + (lane & 3) * 2;
    int n  = nt * 8 + (lane >> 2);
    float beta = logf(THETA / (float)(l + 1) + 1.0f);
    uint32_t h2[2];
#pragma unroll
    for (int p = 0; p < 2; p++) {
        int ka = k0 + p * 8, kb = ka + 1;
        float v0 = beta * convW[l * 16384 + ka * 128 + n] + ((ka == n) ? (1.0f - beta) : 0.0f);
        float v1 = beta * convW[l * 16384 + kb * 128 + n] + ((kb == n) ? (1.0f - beta) : 0.0f);
        h2[p] = pack_half2(v0, v1);
    }
    g_B16h[i] = make_uint2(h2[0], h2[1]);
}

// ---------------- split x into bf16 hi/lo (input GEMM A); also zero CSR counters --------
__global__ void k_splitx(const float* __restrict__ x) {
    int i = blockIdx.x * blockDim.x + threadIdx.x;
    if (i < NN) g_cnt[i] = 0;                 // folded k_zero_cnt
    if (i >= NN * 64) return;
    float2 v = ((const float2*)x)[i];
    uint32_t lo, hi = pack_split(v.x, v.y, lo);
    g_Ahi[i] = hi;
    g_Alo[i] = lo;
}

// ---------------- CSR build ----------------
__global__ void k_hist(const int* __restrict__ erow) {
    int e = blockIdx.x * blockDim.x + threadIdx.x;
    if (e < EE) atomicAdd(&g_cnt[erow[e]], 1);
}
__global__ void k_scanA() {  // blockDim = 1024
    __shared__ int s[1024];
    int t = threadIdx.x;
    int i = blockIdx.x * 1024 + t;
    int v = (i < NN) ? g_cnt[i] : 0;
    s[t] = v;
    __syncthreads();
    for (int off = 1; off < 1024; off <<= 1) {
        int x = 0;
        if (t >= off) x = s[t - off];
        __syncthreads();
        if (t >= off) s[t] += x;
        __syncthreads();
    }
    if (i < NN) g_ptr[i] = s[t] - v;
    if (t == 1023) g_csum[blockIdx.x] = s[1023];
}
__global__ void k_scanB(int nchunks) {
    int run = 0;
    for (int b = 0; b < nchunks; b++) { int c = g_csum[b]; g_csum[b] = run; run += c; }
    g_ptr[NN] = run;
}
__global__ void k_scanC() {
    int i = blockIdx.x * blockDim.x + threadIdx.x;
    if (i < NN) { g_ptr[i] += g_csum[i >> 10]; g_cnt[i] = 0; }
}
__global__ void k_scatter(const int* __restrict__ erow, const int* __restrict__ ecol,
                          const float* __restrict__ ew) {
    int e = blockIdx.x * blockDim.x + threadIdx.x;
    if (e >= EE) return;
    int r = erow[e];
    int p = g_ptr[r] + atomicAdd(&g_cnt[r], 1);
    g_cw[p] = make_int2(ecol[e], __float_as_int(ew[e]));
}

// ---------------- input GEMM (bf16 3-term, single-barrier): x0,h (fp16) = relu(xW+b) ----
#define SMEM_BYTES 65536

__global__ void __launch_bounds__(256, 2) k_mma(const float* __restrict__ bias)
{
    extern __shared__ char smem[];
    uint32_t aBase = smem_u32(smem);
    int tid = threadIdx.x, wid = tid >> 5, lane = tid & 31;
    int wm = wid & 1, wn = wid >> 1;
    int m0 = blockIdx.x * 128;

    {
        int strow = tid >> 1, sth = tid & 1;
        uint32_t stDst = aBase + ((((strow << 1) + sth) ^ ((strow >> 2) & 1)) << 4);
        size_t stSrcBase = (size_t)(m0 + strow) * 64 + sth * 4;
#pragma unroll
        for (int s = 0; s < 8; s++) {
            cp16(stDst + (uint32_t)s * 8192, g_Ahi + stSrcBase + (size_t)s * 8);
            cp16(stDst + (uint32_t)s * 8192 + 4096, g_Alo + stSrcBase + (size_t)s * 8);
        }
        CP_COMMIT();
    }

    float acc[4][4][4];
#pragma unroll
    for (int a = 0; a < 4; a++)
#pragma unroll
        for (int b = 0; b < 4; b++)
#pragma unroll
            for (int c = 0; c < 4; c++) acc[a][b][c] = 0.f;

    uint32_t lmAddr[4];
    {
        int sub = lane >> 3;
        int rin = (sub & 1) * 8 + (lane & 7);
        int h = sub >> 1;
#pragma unroll
        for (int mt = 0; mt < 4; mt++) {
            int row = wm * 64 + mt * 16 + rin;
            lmAddr[mt] = aBase + ((((row << 1) + h) ^ ((row >> 2) & 1)) << 4);
        }
    }

    const uint2* __restrict__ Bh = g_Bfh;
    const uint2* __restrict__ Bl = g_Bfl;
    uint2 bh[4], bl[4];
#pragma unroll
    for (int nt = 0; nt < 4; nt++) {
        int bi = (wn * 4 + nt) * 32 + lane;
        bh[nt] = Bh[bi];
        bl[nt] = Bl[bi];
    }

    CP_WAIT(0);
    __syncthreads();

#pragma unroll
    for (int s = 0; s < 8; s++) {
        uint2 bh2[4], bl2[4];
        if (s < 7) {
#pragma unroll
            for (int nt = 0; nt < 4; nt++) {
                int bi = ((s + 1) * 16 + wn * 4 + nt) * 32 + lane;
                bh2[nt] = Bh[bi];
                bl2[nt] = Bl[bi];
            }
        }
        uint32_t bufOff = (uint32_t)s * 8192;
#pragma unroll
        for (int mt = 0; mt < 4; mt++) {
            uint32_t ah[4], al[4];
            LDMATRIX_X4(ah, lmAddr[mt] + bufOff);
            LDMATRIX_X4(al, lmAddr[mt] + bufOff + 4096);
#pragma unroll
            for (int nt = 0; nt < 4; nt++) {
                MMA16816(acc[mt][nt], ah[0], ah[1], ah[2], ah[3], bh[nt].x, bh[nt].y);
                MMA16816(acc[mt][nt], ah[0], ah[1], ah[2], ah[3], bl[nt].x, bl[nt].y);
                MMA16816(acc[mt][nt], al[0], al[1], al[2], al[3], bh[nt].x, bh[nt].y);
            }
        }
        if (s < 7) {
#pragma unroll
            for (int nt = 0; nt < 4; nt++) { bh[nt] = bh2[nt]; bl[nt] = bl2[nt]; }
        }
    }

    int rowb = m0 + wm * 64 + (lane >> 2);
    int cb   = (lane & 3) * 2;
#pragma unroll
    for (int mt = 0; mt < 4; mt++) {
        int r1 = rowb + mt * 16, r2 = r1 + 8;
#pragma unroll
        for (int nt = 0; nt < 4; nt++) {
            int cn = wn * 32 + nt * 8 + cb;
            float b0 = bias[cn], b1 = bias[cn + 1];
            float d0 = fmaxf(acc[mt][nt][0] + b0, 0.f);
            float d1 = fmaxf(acc[mt][nt][1] + b1, 0.f);
            float d2 = fmaxf(acc[mt][nt][2] + b0, 0.f);
            float d3 = fmaxf(acc[mt][nt][3] + b1, 0.f);
            uint32_t p1 = pack_half2(d0, d1);
            uint32_t p2 = pack_half2(d2, d3);
            if (r1 < NN) {
                g_x0h[(size_t)r1 * 64 + (cn >> 1)] = p1;
                g_hh [(size_t)r1 * 64 + (cn >> 1)] = p1;
            }
            if (r2 < NN) {
                g_x0h[(size_t)r2 * 64 + (cn >> 1)] = p2;
                g_hh [(size_t)r2 * 64 + (cn >> 1)] = p2;
            }
        }
    }
}

// ---------------- layer GEMM: pure fp16, 1 MMA per fragment, single-barrier + BN stats --
#define SMEM16 32768

__global__ void __launch_bounds__(256, 2) k_mma16(int layer, float* __restrict__ C0)
{
    extern __shared__ char smem[];
    uint32_t aBase = smem_u32(smem);
    int tid = threadIdx.x, wid = tid >> 5, lane = tid & 31;
    int wm = wid & 1, wn = wid >> 1;
    int m0 = blockIdx.x * 128;

    {
        int strow = tid >> 1, sth = tid & 1;
        uint32_t stDst = aBase + ((((strow << 1) + sth) ^ ((strow >> 2) & 1)) << 4);
        size_t src = (size_t)(m0 + strow) * 64 + sth * 4;
#pragma unroll
        for (int s = 0; s < 8; s++)
            cp16(stDst + (uint32_t)s * 4096, g_A16h + src + (size_t)s * 8);
        CP_COMMIT();
    }

    float acc[4][4][4];
#pragma unroll
    for (int a = 0; a < 4; a++)
#pragma unroll
        for (int b = 0; b < 4; b++)
#pragma unroll
            for (int c = 0; c < 4; c++) acc[a][b][c] = 0.f;

    uint32_t lmAddr[4];
    {
        int sub = lane >> 3;
        int rin = (sub & 1) * 8 + (lane & 7);
        int h = sub >> 1;
#pragma unroll
        for (int mt = 0; mt < 4; mt++) {
            int row = wm * 64 + mt * 16 + rin;
            lmAddr[mt] = aBase + ((((row << 1) + h) ^ ((row >> 2) & 1)) << 4);
        }
    }

    const uint2* __restrict__ Bh = g_B16h + (size_t)layer * 4096;
    uint2 bh[4];
#pragma unroll
    for (int nt = 0; nt < 4; nt++)
        bh[nt] = Bh[(wn * 4 + nt) * 32 + lane];

    CP_WAIT(0);
    __syncthreads();   // the ONLY barrier

#pragma unroll
    for (int s = 0; s < 8; s++) {
        uint2 bh2[4];
        if (s < 7) {
#pragma unroll
            for (int nt = 0; nt < 4; nt++)
                bh2[nt] = Bh[((s + 1) * 16 + wn * 4 + nt) * 32 + lane];
        }
        uint32_t bufOff = (uint32_t)s * 4096;
#pragma unroll
        for (int mt = 0; mt < 4; mt++) {
            uint32_t ah[4];
            LDMATRIX_X4(ah, lmAddr[mt] + bufOff);
#pragma unroll
            for (int nt = 0; nt < 4; nt++)
                MMA16816H(acc[mt][nt], ah[0], ah[1], ah[2], ah[3], bh[nt].x, bh[nt].y);
        }
        if (s < 7) {
#pragma unroll
            for (int nt = 0; nt < 4; nt++) bh[nt] = bh2[nt];
        }
    }

    int rowb = m0 + wm * 64 + (lane >> 2);
    int cb   = (lane & 3) * 2;
#pragma unroll
    for (int mt = 0; mt < 4; mt++) {
        int r1 = rowb + mt * 16, r2 = r1 + 8;
#pragma unroll
        for (int nt = 0; nt < 4; nt++) {
            int cn = wn * 32 + nt * 8 + cb;
            if (r1 < NN)
                *(float2*)&C0[(size_t)r1 * DH + cn] = make_float2(acc[mt][nt][0], acc[mt][nt][1]);
            if (r2 < NN)
                *(float2*)&C0[(size_t)r2 * DH + cn] = make_float2(acc[mt][nt][2], acc[mt][nt][3]);
        }
    }
    // BN partial sums (pad rows: A zero -> acc 0 -> contribute 0)
#pragma unroll
    for (int nt = 0; nt < 4; nt++) {
        float s0 = 0.f, s1 = 0.f, q0 = 0.f, q1 = 0.f;
#pragma unroll
        for (int mt = 0; mt < 4; mt++) {
            float d0 = acc[mt][nt][0], d1 = acc[mt][nt][1];
            float d2 = acc[mt][nt][2], d3 = acc[mt][nt][3];
            s0 += d0 + d2; s1 += d1 + d3;
            q0 += d0 * d0 + d2 * d2; q1 += d1 * d1 + d3 * d3;
        }
#pragma unroll
        for (int off = 4; off < 32; off <<= 1) {
            s0 += __shfl_xor_sync(0xffffffffu, s0, off);
            s1 += __shfl_xor_sync(0xffffffffu, s1, off);
            q0 += __shfl_xor_sync(0xffffffffu, q0, off);
            q1 += __shfl_xor_sync(0xffffffffu, q1, off);
        }
        if (lane < 4) {
            int cn = wn * 32 + nt * 8 + lane * 2;
            atomicAdd(&g_sum[cn],     s0);
            atomicAdd(&g_sum[cn + 1], s1);
            atomicAdd(&g_sq[cn],      q0);
            atomicAdd(&g_sq[cn + 1],  q1);
        }
    }
}

// ---------------- SpMM: a = (1-ALPHA)*(A_hat @ h) + ALPHA*x0, fp16 in/out, unroll-8 -----
__global__ void __launch_bounds__(256) k_spmm() {
    if (blockIdx.x == 0 && threadIdx.x < 128) {
        g_sum[threadIdx.x] = 0.f;
        g_sq[threadIdx.x]  = 0.f;
    }
    int wid = (blockIdx.x * blockDim.x + threadIdx.x) >> 5;
    int lane = threadIdx.x & 31;
    if (wid >= NN) return;
    int s = g_ptr[wid], e = g_ptr[wid + 1];
    const uint2* __restrict__ h2 = (const uint2*)g_hh;
    const int2* __restrict__ cw = g_cw;

    uint2 xv = ((const uint2*)g_x0h)[(size_t)wid * 32 + lane];
    float2 x01 = unpack_half2(xv.x), x23 = unpack_half2(xv.y);

    float4 acc = make_float4(0.f, 0.f, 0.f, 0.f);
    int p = s;
    int e8 = s + ((e - s) & ~7);
    for (; p < e8; p += 8) {
        uint2 u[8];
        float w[8];
#pragma unroll
        for (int j = 0; j < 8; j++) {
            int2 c = cw[p + j];
            w[j] = __int_as_float(c.y);
            u[j] = h2[(size_t)c.x * 32 + lane];
        }
#pragma unroll
        for (int j = 0; j < 8; j++) {
            float2 a = unpack_half2(u[j].x), b = unpack_half2(u[j].y);
            acc.x += w[j] * a.x; acc.y += w[j] * a.y;
            acc.z += w[j] * b.x; acc.w += w[j] * b.y;
        }
    }
    int e4 = p + ((e - p) & ~3);
    for (; p < e4; p += 4) {
        uint2 u[4];
        float w[4];
#pragma unroll
        for (int j = 0; j < 4; j++) {
            int2 c = cw[p + j];
            w[j] = __int_as_float(c.y);
            u[j] = h2[(size_t)c.x * 32 + lane];
        }
#pragma unroll
        for (int j = 0; j < 4; j++) {
            float2 a = unpack_half2(u[j].x), b = unpack_half2(u[j].y);
            acc.x += w[j] * a.x; acc.y += w[j] * a.y;
            acc.z += w[j] * b.x; acc.w += w[j] * b.y;
        }
    }
    for (; p < e; p++) {
        int2 c = cw[p];
        float w = __int_as_float(c.y);
        uint2 u = h2[(size_t)c.x * 32 + lane];
        float2 a = unpack_half2(u.x), b = unpack_half2(u.y);
        acc.x += w * a.x; acc.y += w * a.y; acc.z += w * b.x; acc.w += w * b.y;
    }
    float ox = (1.f - ALPHA) * acc.x + ALPHA * x01.x;
    float oy = (1.f - ALPHA) * acc.y + ALPHA * x01.y;
    float oz = (1.f - ALPHA) * acc.z + ALPHA * x23.x;
    float ow = (1.f - ALPHA) * acc.w + ALPHA * x23.y;
    ((uint2*)g_A16h)[(size_t)wid * 32 + lane] =
        make_uint2(pack_half2(ox, oy), pack_half2(oz, ow));
}

// ---------------- BN apply + residual + relu; h fp16; 2 elems/thread ----------------
__global__ void __launch_bounds__(256) k_bnapply(const float* __restrict__ gamma,
                                                 const float* __restrict__ bbeta, int l) {
    __shared__ float sc[128], sh[128];
    int t = threadIdx.x;
    if (t < 128) {
        float mu = g_sum[t] * (1.0f / NN);
        float var = g_sq[t] * (1.0f / NN) - mu * mu;
        float s = gamma[l * DH + t] * rsqrtf(var + BN_EPS);
        sc[t] = s;
        sh[t] = bbeta[l * DH + t] - mu * s;
    }
    __syncthreads();
    int i0 = blockIdx.x * 512 + t;
#pragma unroll
    for (int u = 0; u < 2; u++) {
        int i = i0 + u * 256;
        if (i >= NN * 32) return;
        int fb = (i & 31) << 2;
        float4 a = ((const float4*)g_a2)[i];
        uint2 hv = ((const uint2*)g_hh)[i];
        float2 h01 = unpack_half2(hv.x), h23 = unpack_half2(hv.y);
        float4 scv = *(float4*)&sc[fb];
        float4 shv = *(float4*)&sh[fb];
        float o0 = fmaxf(fmaf(a.x, scv.x, shv.x) + h01.x, 0.f);
        float o1 = fmaxf(fmaf(a.y, scv.y, shv.y) + h01.y, 0.f);
        float o2 = fmaxf(fmaf(a.z, scv.z, shv.z) + h23.x, 0.f);
        float o3 = fmaxf(fmaf(a.w, scv.w, shv.w) + h23.y, 0.f);
        ((uint2*)g_hh)[i] = make_uint2(pack_half2(o0, o1), pack_half2(o2, o3));
    }
}

// ---------------- output GEMM: out[N,40] = h @ W_out + b_out (h fp16) ----------------
__global__ void __launch_bounds__(256) k_out(const float* __restrict__ Wout,
                                             const float* __restrict__ bout,
                                             float* __restrict__ out) {
    __shared__ float Hs[32][132];
    __shared__ float Ws[DH * DOUT];
    __shared__ float Bs[DOUT];
    int tid = threadIdx.x;
    int m0 = blockIdx.x * 32;
    for (int j = tid; j < DH * DOUT; j += 256) Ws[j] = Wout[j];
    if (tid < DOUT) Bs[tid] = bout[tid];
#pragma unroll
    for (int j = 0; j < 4; j++) {
        int flat = tid + j * 256;
        int r = flat >> 5, c4 = flat & 31;
        int gr = m0 + r;
        float4 v = make_float4(0.f, 0.f, 0.f, 0.f);
        if (gr < NN) {
            uint2 u = ((const uint2*)g_hh)[(size_t)gr * 32 + c4];
            float2 f01 = unpack_half2(u.x), f23 = unpack_half2(u.y);
            v = make_float4(f01.x, f01.y, f23.x, f23.y);
        }
        *(float4*)&Hs[r][c4 << 2] = v;
    }
    __syncthreads();
    int r = tid >> 3;
    int cg = tid & 7;
    float acc[5] = {0.f, 0.f, 0.f, 0.f, 0.f};
    for (int k = 0; k < DH; k++) {
        float a = Hs[r][k];
#pragma unroll
        for (int j = 0; j < 5; j++) acc[j] += a * Ws[k * DOUT + cg * 5 + j];
    }
    int gr = m0 + r;
    if (gr < NN) {
#pragma unroll
        for (int j = 0; j < 5; j++)
            out[(size_t)gr * DOUT + cg * 5 + j] = acc[j] + Bs[cg * 5 + j];
    }
}

// ---------------- launch ----------------
extern "C" void kernel_launch(void* const* d_in, const int* in_sizes, int n_in,
                              void* d_out, int out_size) {
    const float* x     = (const float*)d_in[0];
    const float* ew    = (const float*)d_in[1];
    const float* W_in  = (const float*)d_in[2];
    const float* b_in  = (const float*)d_in[3];
    const float* convW = (const float*)d_in[4];
    const float* gamma = (const float*)d_in[5];
    const float* bbeta = (const float*)d_in[6];
    const float* W_out = (const float*)d_in[7];
    const float* b_out = (const float*)d_in[8];
    const int*   erow  = (const int*)d_in[9];
    const int*   ecol  = (const int*)d_in[10];
    float* out = (float*)d_out;

    float* p_a2;
    cudaGetSymbolAddress((void**)&p_a2, g_a2);

    cudaFuncSetAttribute(k_mma, cudaFuncAttributeMaxDynamicSharedMemorySize, SMEM_BYTES);
    cudaFuncSetAttribute(k_mma16, cudaFuncAttributeMaxDynamicSharedMemorySize, SMEM16);

    const int nchunks = (NN + 1023) / 1024;  // 98
    const int ngemm = (NN + 127) / 128;      // 782

    k_prep_bin<<<16, 256>>>(W_in);
    k_prep_b16<<<(NLAYERS * 4096 + 255) / 256, 256>>>(convW);
    k_splitx<<<(NN * 64 + 255) / 256, 256>>>(x);
    // 4th launch = ncu slot: DUMMY k_spmm for profiling. First run: g_ptr is zero ->
    // empty rows, writes alpha*x0 to g_A16h which the real layer-0 spmm overwrites
    // before any read. Replays: reads prior-run h/CSR deterministically. Output-safe.
    k_spmm<<<(NN * 32 + 255) / 256, 256>>>();

    k_mma<<<ngemm, 256, SMEM_BYTES>>>(b_in);
    k_hist<<<(EE + 255) / 256, 256>>>(erow);
    k_scanA<<<nchunks, 1024>>>();
    k_scanB<<<1, 1>>>(nchunks);
    k_scanC<<<(NN + 255) / 256, 256>>>();
    k_scatter<<<(EE + 255) / 256, 256>>>(erow, ecol, ew);

    for (int l = 0; l < NLAYERS; l++) {
        k_spmm<<<(NN * 32 + 255) / 256, 256>>>();
        k_mma16<<<ngemm, 256, SMEM16>>>(l, p_a2);
        k_bnapply<<<(NN * 32 + 511) / 512, 256>>>(gamma, bbeta, l);
    }

    k_out<<<(NN + 31) / 32, 256>>>(W_out, b_out, out);
}

// round 17
// speedup vs baseline: 1.1041x; 1.1041x over previous
#include <cuda_runtime.h>
#include <cuda_bf16.h>
#include <cuda_fp16.h>
#include <math.h>
#include <stdint.h>

#define NN 100000
#define EE 800000
#define DH 128
#define DOUT 40
#define NLAYERS 16
#define ALPHA 0.1f
#define THETA 0.5f
#define BN_EPS 1e-5f
#define NN_PAD (782 * 128)

// ---------------- scratch (device globals; zero-initialized at load) ----------------
__device__ uint32_t g_x0h[(size_t)NN * 64];       // x0 as half2 pairs
__device__ uint32_t g_hh [(size_t)NN * 64];       // h  as half2 pairs
__device__ float    g_a2[(size_t)NN * DH];        // layer GEMM output (fp32)
// input GEMM (bf16 3-term) operands
__device__ uint32_t g_Ahi[(size_t)NN_PAD * 64];   // bf16x2 hi-split of x
__device__ uint32_t g_Alo[(size_t)NN_PAD * 64];
__device__ uint2    g_Bfh[4096];                   // W_in bf16 hi frags
__device__ uint2    g_Bfl[4096];                   // W_in bf16 lo frags
// layer GEMMs: pure fp16 (1 MMA per fragment)
__device__ uint32_t g_A16h[(size_t)NN_PAD * 64];   // fp16 of spmm output
__device__ uint2    g_B16h[NLAYERS * 4096];        // fp16(Wp) frags
__device__ int   g_ptr[NN + 1];
__device__ int   g_cnt[NN];
__device__ int   g_col[EE];
__device__ float g_w  [EE];
__device__ int   g_csum[128];
__device__ float g_sum[DH], g_sq[DH];

// ---------------- helpers ----------------
__device__ __forceinline__ uint32_t smem_u32(const void* p) {
    uint32_t a;
    asm("{ .reg .u64 t; cvta.to.shared.u64 t, %1; cvt.u32.u64 %0, t; }" : "=r"(a) : "l"(p));
    return a;
}
__device__ __forceinline__ uint32_t pack_split(float a, float b, uint32_t& lo_out) {
    __nv_bfloat162 hi2 = __float22bfloat162_rn(make_float2(a, b));
    float ra = a - __bfloat162float(hi2.x);
    float rb = b - __bfloat162float(hi2.y);
    __nv_bfloat162 lo2 = __float22bfloat162_rn(make_float2(ra, rb));
    lo_out = *(uint32_t*)&lo2;
    return *(uint32_t*)&hi2;
}
__device__ __forceinline__ uint32_t pack_half2(float a, float b) {
    __half2 h = __float22half2_rn(make_float2(a, b));
    return *(uint32_t*)&h;
}
__device__ __forceinline__ float2 unpack_half2(uint32_t v) {
    return __half22float2(*(__half2*)&v);
}

#define MMA16816(D, A0, A1, A2, A3, B0, B1) \
    asm volatile("mma.sync.aligned.m16n8k16.row.col.f32.bf16.bf16.f32 " \
        "{%0,%1,%2,%3}, {%4,%5,%6,%7}, {%8,%9}, {%0,%1,%2,%3};" \
        : "+f"((D)[0]), "+f"((D)[1]), "+f"((D)[2]), "+f"((D)[3]) \
        : "r"(A0), "r"(A1), "r"(A2), "r"(A3), "r"(B0), "r"(B1))

#define MMA16816H(D, A0, A1, A2, A3, B0, B1) \
    asm volatile("mma.sync.aligned.m16n8k16.row.col.f32.f16.f16.f32 " \
        "{%0,%1,%2,%3}, {%4,%5,%6,%7}, {%8,%9}, {%0,%1,%2,%3};" \
        : "+f"((D)[0]), "+f"((D)[1]), "+f"((D)[2]), "+f"((D)[3]) \
        : "r"(A0), "r"(A1), "r"(A2), "r"(A3), "r"(B0), "r"(B1))

#define LDMATRIX_X4(R, addr) \
    asm volatile("ldmatrix.sync.aligned.m8n8.x4.shared.b16 {%0,%1,%2,%3}, [%4];" \
        : "=r"((R)[0]), "=r"((R)[1]), "=r"((R)[2]), "=r"((R)[3]) : "r"(addr))

__device__ __forceinline__ void cp16(uint32_t dst, const void* src) {
    asm volatile("cp.async.cg.shared.global [%0], [%1], 16;" :: "r"(dst), "l"(src));
}
#define CP_COMMIT() asm volatile("cp.async.commit_group;" ::: "memory")
#define CP_WAIT(n)  asm volatile("cp.async.wait_group %0;" :: "n"(n) : "memory")

// ---------------- weight prep: input GEMM (bf16 3-term, W_in) ----------------
__global__ void k_prep_bin(const float* __restrict__ W_in) {
    int i = blockIdx.x * blockDim.x + threadIdx.x;
    if (i >= 4096) return;
    int lane = i & 31;
    int nt   = (i >> 5) & 15;
    int s    = (i >> 9) & 7;
    int k0 = s * 16 + (lane & 3) * 2;
    int n  = nt * 8 + (lane >> 2);
    float v[4];
#pragma unroll
    for (int j = 0; j < 4; j++) {
        int k = k0 + (j & 1) + (j >> 1) * 8;
        v[j] = W_in[k * 128 + n];
    }
    uint32_t loA, loB;
    uint32_t hiA = pack_split(v[0], v[1], loA);
    uint32_t hiB = pack_split(v[2], v[3], loB);
    g_Bfh[i] = make_uint2(hiA, hiB);
    g_Bfl[i] = make_uint2(loA, loB);
}

// ---------------- weight prep: layers (fp16 fold + fragment pack) ----------------
__global__ void k_prep_b16(const float* __restrict__ convW) {
    int i = blockIdx.x * blockDim.x + threadIdx.x;
    if (i >= NLAYERS * 4096) return;
    int lane = i & 31;
    int nt   = (i >> 5) & 15;
    int s    = (i >> 9) & 7;
    int l    = i >> 12;
    int k0 = s * 16 + (lane & 3) * 2;
    int n  = nt * 8 + (lane >> 2);
    float beta = logf(THETA / (float)(l + 1) + 1.0f);
    uint32_t h2[2];
#pragma unroll
    for (int p = 0; p < 2; p++) {
        int ka = k0 + p * 8, kb = ka + 1;
        float v0 = beta * convW[l * 16384 + ka * 128 + n] + ((ka == n) ? (1.0f - beta) : 0.0f);
        float v1 = beta * convW[l * 16384 + kb * 128 + n] + ((kb == n) ? (1.0f - beta) : 0.0f);
        h2[p] = pack_half2(v0, v1);
    }
    g_B16h[i] = make_uint2(h2[0], h2[1]);
}

// ---------------- split x into bf16 hi/lo (input GEMM A); also zero CSR counters --------
__global__ void k_splitx(const float* __restrict__ x) {
    int i = blockIdx.x * blockDim.x + threadIdx.x;
    if (i < NN) g_cnt[i] = 0;                 // folded k_zero_cnt
    if (i >= NN * 64) return;
    float2 v = ((const float2*)x)[i];
    uint32_t lo, hi = pack_split(v.x, v.y, lo);
    g_Ahi[i] = hi;
    g_Alo[i] = lo;
}

// ---------------- CSR build ----------------
__global__ void k_hist(const int* __restrict__ erow) {
    int e = blockIdx.x * blockDim.x + threadIdx.x;
    if (e < EE) atomicAdd(&g_cnt[erow[e]], 1);
}
__global__ void k_scanA() {  // blockDim = 1024
    __shared__ int s[1024];
    int t = threadIdx.x;
    int i = blockIdx.x * 1024 + t;
    int v = (i < NN) ? g_cnt[i] : 0;
    s[t] = v;
    __syncthreads();
    for (int off = 1; off < 1024; off <<= 1) {
        int x = 0;
        if (t >= off) x = s[t - off];
        __syncthreads();
        if (t >= off) s[t] += x;
        __syncthreads();
    }
    if (i < NN) g_ptr[i] = s[t] - v;
    if (t == 1023) g_csum[blockIdx.x] = s[1023];
}
// merged scanB+scanC: every block redundantly scans the 98 chunk sums in smem,
// then adds the chunk prefix to its g_ptr entries and re-zeroes cursors.
__global__ void k_scanBC() {
    __shared__ int s[128];
    int t = threadIdx.x;
    if (t < 128) s[t] = (t < 98) ? g_csum[t] : 0;
    __syncthreads();
    for (int off = 1; off < 128; off <<= 1) {
        int x = 0;
        if (t < 128 && t >= off) x = s[t - off];
        __syncthreads();
        if (t < 128 && t >= off) s[t] += x;
        __syncthreads();
    }
    int i = blockIdx.x * blockDim.x + t;
    if (i == 0) g_ptr[NN] = EE;
    if (i < NN) {
        int c = i >> 10;
        int pre = (c == 0) ? 0 : s[c - 1];
        g_ptr[i] += pre;
        g_cnt[i] = 0;  // scatter cursor
    }
}
__global__ void k_scatter(const int* __restrict__ erow, const int* __restrict__ ecol,
                          const float* __restrict__ ew) {
    int e = blockIdx.x * blockDim.x + threadIdx.x;
    if (e >= EE) return;
    int r = erow[e];
    int p = g_ptr[r] + atomicAdd(&g_cnt[r], 1);
    g_col[p] = ecol[e];
    g_w[p]   = ew[e];
}

// ---------------- input GEMM (bf16 3-term, single-barrier): x0,h (fp16) = relu(xW+b) ----
#define SMEM_BYTES 65536

__global__ void __launch_bounds__(256, 2) k_mma(const float* __restrict__ bias)
{
    extern __shared__ char smem[];
    uint32_t aBase = smem_u32(smem);
    int tid = threadIdx.x, wid = tid >> 5, lane = tid & 31;
    int wm = wid & 1, wn = wid >> 1;
    int m0 = blockIdx.x * 128;

    {
        int strow = tid >> 1, sth = tid & 1;
        uint32_t stDst = aBase + ((((strow << 1) + sth) ^ ((strow >> 2) & 1)) << 4);
        size_t stSrcBase = (size_t)(m0 + strow) * 64 + sth * 4;
#pragma unroll
        for (int s = 0; s < 8; s++) {
            cp16(stDst + (uint32_t)s * 8192, g_Ahi + stSrcBase + (size_t)s * 8);
            cp16(stDst + (uint32_t)s * 8192 + 4096, g_Alo + stSrcBase + (size_t)s * 8);
        }
        CP_COMMIT();
    }

    float acc[4][4][4];
#pragma unroll
    for (int a = 0; a < 4; a++)
#pragma unroll
        for (int b = 0; b < 4; b++)
#pragma unroll
            for (int c = 0; c < 4; c++) acc[a][b][c] = 0.f;

    uint32_t lmAddr[4];
    {
        int sub = lane >> 3;
        int rin = (sub & 1) * 8 + (lane & 7);
        int h = sub >> 1;
#pragma unroll
        for (int mt = 0; mt < 4; mt++) {
            int row = wm * 64 + mt * 16 + rin;
            lmAddr[mt] = aBase + ((((row << 1) + h) ^ ((row >> 2) & 1)) << 4);
        }
    }

    const uint2* __restrict__ Bh = g_Bfh;
    const uint2* __restrict__ Bl = g_Bfl;
    uint2 bh[4], bl[4];
#pragma unroll
    for (int nt = 0; nt < 4; nt++) {
        int bi = (wn * 4 + nt) * 32 + lane;
        bh[nt] = Bh[bi];
        bl[nt] = Bl[bi];
    }

    CP_WAIT(0);
    __syncthreads();

#pragma unroll
    for (int s = 0; s < 8; s++) {
        uint2 bh2[4], bl2[4];
        if (s < 7) {
#pragma unroll
            for (int nt = 0; nt < 4; nt++) {
                int bi = ((s + 1) * 16 + wn * 4 + nt) * 32 + lane;
                bh2[nt] = Bh[bi];
                bl2[nt] = Bl[bi];
            }
        }
        uint32_t bufOff = (uint32_t)s * 8192;
#pragma unroll
        for (int mt = 0; mt < 4; mt++) {
            uint32_t ah[4], al[4];
            LDMATRIX_X4(ah, lmAddr[mt] + bufOff);
            LDMATRIX_X4(al, lmAddr[mt] + bufOff + 4096);
#pragma unroll
            for (int nt = 0; nt < 4; nt++) {
                MMA16816(acc[mt][nt], ah[0], ah[1], ah[2], ah[3], bh[nt].x, bh[nt].y);
                MMA16816(acc[mt][nt], ah[0], ah[1], ah[2], ah[3], bl[nt].x, bl[nt].y);
                MMA16816(acc[mt][nt], al[0], al[1], al[2], al[3], bh[nt].x, bh[nt].y);
            }
        }
        if (s < 7) {
#pragma unroll
            for (int nt = 0; nt < 4; nt++) { bh[nt] = bh2[nt]; bl[nt] = bl2[nt]; }
        }
    }

    int rowb = m0 + wm * 64 + (lane >> 2);
    int cb   = (lane & 3) * 2;
#pragma unroll
    for (int mt = 0; mt < 4; mt++) {
        int r1 = rowb + mt * 16, r2 = r1 + 8;
#pragma unroll
        for (int nt = 0; nt < 4; nt++) {
            int cn = wn * 32 + nt * 8 + cb;
            float b0 = bias[cn], b1 = bias[cn + 1];
            float d0 = fmaxf(acc[mt][nt][0] + b0, 0.f);
            float d1 = fmaxf(acc[mt][nt][1] + b1, 0.f);
            float d2 = fmaxf(acc[mt][nt][2] + b0, 0.f);
            float d3 = fmaxf(acc[mt][nt][3] + b1, 0.f);
            uint32_t p1 = pack_half2(d0, d1);
            uint32_t p2 = pack_half2(d2, d3);
            if (r1 < NN) {
                g_x0h[(size_t)r1 * 64 + (cn >> 1)] = p1;
                g_hh [(size_t)r1 * 64 + (cn >> 1)] = p1;
            }
            if (r2 < NN) {
                g_x0h[(size_t)r2 * 64 + (cn >> 1)] = p2;
                g_hh [(size_t)r2 * 64 + (cn >> 1)] = p2;
            }
        }
    }
}

// ---------------- layer GEMM: pure fp16, 1 MMA per fragment, single-barrier + BN stats --
#define SMEM16 32768

__global__ void __launch_bounds__(256, 2) k_mma16(int layer, float* __restrict__ C0)
{
    extern __shared__ char smem[];
    uint32_t aBase = smem_u32(smem);
    int tid = threadIdx.x, wid = tid >> 5, lane = tid & 31;
    int wm = wid & 1, wn = wid >> 1;
    int m0 = blockIdx.x * 128;

    {
        int strow = tid >> 1, sth = tid & 1;
        uint32_t stDst = aBase + ((((strow << 1) + sth) ^ ((strow >> 2) & 1)) << 4);
        size_t src = (size_t)(m0 + strow) * 64 + sth * 4;
#pragma unroll
        for (int s = 0; s < 8; s++)
            cp16(stDst + (uint32_t)s * 4096, g_A16h + src + (size_t)s * 8);
        CP_COMMIT();
    }

    float acc[4][4][4];
#pragma unroll
    for (int a = 0; a < 4; a++)
#pragma unroll
        for (int b = 0; b < 4; b++)
#pragma unroll
            for (int c = 0; c < 4; c++) acc[a][b][c] = 0.f;

    uint32_t lmAddr[4];
    {
        int sub = lane >> 3;
        int rin = (sub & 1) * 8 + (lane & 7);
        int h = sub >> 1;
#pragma unroll
        for (int mt = 0; mt < 4; mt++) {
            int row = wm * 64 + mt * 16 + rin;
            lmAddr[mt] = aBase + ((((row << 1) + h) ^ ((row >> 2) & 1)) << 4);
        }
    }

    const uint2* __restrict__ Bh = g_B16h + (size_t)layer * 4096;
    uint2 bh[4];
#pragma unroll
    for (int nt = 0; nt < 4; nt++)
        bh[nt] = Bh[(wn * 4 + nt) * 32 + lane];

    CP_WAIT(0);
    __syncthreads();   // the ONLY barrier

#pragma unroll
    for (int s = 0; s < 8; s++) {
        uint2 bh2[4];
        if (s < 7) {
#pragma unroll
            for (int nt = 0; nt < 4; nt++)
                bh2[nt] = Bh[((s + 1) * 16 + wn * 4 + nt) * 32 + lane];
        }
        uint32_t bufOff = (uint32_t)s * 4096;
#pragma unroll
        for (int mt = 0; mt < 4; mt++) {
            uint32_t ah[4];
            LDMATRIX_X4(ah, lmAddr[mt] + bufOff);
#pragma unroll
            for (int nt = 0; nt < 4; nt++)
                MMA16816H(acc[mt][nt], ah[0], ah[1], ah[2], ah[3], bh[nt].x, bh[nt].y);
        }
        if (s < 7) {
#pragma unroll
            for (int nt = 0; nt < 4; nt++) bh[nt] = bh2[nt];
        }
    }

    int rowb = m0 + wm * 64 + (lane >> 2);
    int cb   = (lane & 3) * 2;
#pragma unroll
    for (int mt = 0; mt < 4; mt++) {
        int r1 = rowb + mt * 16, r2 = r1 + 8;
#pragma unroll
        for (int nt = 0; nt < 4; nt++) {
            int cn = wn * 32 + nt * 8 + cb;
            if (r1 < NN)
                *(float2*)&C0[(size_t)r1 * DH + cn] = make_float2(acc[mt][nt][0], acc[mt][nt][1]);
            if (r2 < NN)
                *(float2*)&C0[(size_t)r2 * DH + cn] = make_float2(acc[mt][nt][2], acc[mt][nt][3]);
        }
    }
    // BN partial sums (pad rows: A zero -> acc 0 -> contribute 0)
#pragma unroll
    for (int nt = 0; nt < 4; nt++) {
        float s0 = 0.f, s1 = 0.f, q0 = 0.f, q1 = 0.f;
#pragma unroll
        for (int mt = 0; mt < 4; mt++) {
            float d0 = acc[mt][nt][0], d1 = acc[mt][nt][1];
            float d2 = acc[mt][nt][2], d3 = acc[mt][nt][3];
            s0 += d0 + d2; s1 += d1 + d3;
            q0 += d0 * d0 + d2 * d2; q1 += d1 * d1 + d3 * d3;
        }
#pragma unroll
        for (int off = 4; off < 32; off <<= 1) {
            s0 += __shfl_xor_sync(0xffffffffu, s0, off);
            s1 += __shfl_xor_sync(0xffffffffu, s1, off);
            q0 += __shfl_xor_sync(0xffffffffu, q0, off);
            q1 += __shfl_xor_sync(0xffffffffu, q1, off);
        }
        if (lane < 4) {
            int cn = wn * 32 + nt * 8 + lane * 2;
            atomicAdd(&g_sum[cn],     s0);
            atomicAdd(&g_sum[cn + 1], s1);
            atomicAdd(&g_sq[cn],      q0);
            atomicAdd(&g_sq[cn + 1],  q1);
        }
    }
}

// ---------------- SpMM: a = (1-ALPHA)*(A_hat @ h) + ALPHA*x0, fp16 in/out, unroll-8 -----
__global__ void __launch_bounds__(256) k_spmm() {
    if (blockIdx.x == 0 && threadIdx.x < 128) {
        g_sum[threadIdx.x] = 0.f;
        g_sq[threadIdx.x]  = 0.f;
    }
    int wid = (blockIdx.x * blockDim.x + threadIdx.x) >> 5;
    int lane = threadIdx.x & 31;
    if (wid >= NN) return;
    int s = g_ptr[wid], e = g_ptr[wid + 1];
    const uint2* __restrict__ h2 = (const uint2*)g_hh;

    uint2 xv = ((const uint2*)g_x0h)[(size_t)wid * 32 + lane];
    float2 x01 = unpack_half2(xv.x), x23 = unpack_half2(xv.y);

    float4 acc = make_float4(0.f, 0.f, 0.f, 0.f);
    int p = s;
    int e8 = s + ((e - s) & ~7);
    for (; p < e8; p += 8) {
        uint2 u[8];
        float w[8];
#pragma unroll
        for (int j = 0; j < 8; j++) {
            int c = g_col[p + j];
            w[j] = g_w[p + j];
            u[j] = h2[(size_t)c * 32 + lane];
        }
#pragma unroll
        for (int j = 0; j < 8; j++) {
            float2 a = unpack_half2(u[j].x), b = unpack_half2(u[j].y);
            acc.x += w[j] * a.x; acc.y += w[j] * a.y;
            acc.z += w[j] * b.x; acc.w += w[j] * b.y;
        }
    }
    int e4 = p + ((e - p) & ~3);
    for (; p < e4; p += 4) {
        uint2 u[4];
        float w[4];
#pragma unroll
        for (int j = 0; j < 4; j++) {
            int c = g_col[p + j];
            w[j] = g_w[p + j];
            u[j] = h2[(size_t)c * 32 + lane];
        }
#pragma unroll
        for (int j = 0; j < 4; j++) {
            float2 a = unpack_half2(u[j].x), b = unpack_half2(u[j].y);
            acc.x += w[j] * a.x; acc.y += w[j] * a.y;
            acc.z += w[j] * b.x; acc.w += w[j] * b.y;
        }
    }
    for (; p < e; p++) {
        int c = g_col[p];
        float w = g_w[p];
        uint2 u = h2[(size_t)c * 32 + lane];
        float2 a = unpack_half2(u.x), b = unpack_half2(u.y);
        acc.x += w * a.x; acc.y += w * a.y; acc.z += w * b.x; acc.w += w * b.y;
    }
    float ox = (1.f - ALPHA) * acc.x + ALPHA * x01.x;
    float oy = (1.f - ALPHA) * acc.y + ALPHA * x01.y;
    float oz = (1.f - ALPHA) * acc.z + ALPHA * x23.x;
    float ow = (1.f - ALPHA) * acc.w + ALPHA * x23.y;
    ((uint2*)g_A16h)[(size_t)wid * 32 + lane] =
        make_uint2(pack_half2(ox, oy), pack_half2(oz, ow));
}

// ---------------- BN apply + residual + relu; h fp16; 2 elems/thread ----------------
__global__ void __launch_bounds__(256) k_bnapply(const float* __restrict__ gamma,
                                                 const float* __restrict__ bbeta, int l) {
    __shared__ float sc[128], sh[128];
    int t = threadIdx.x;
    if (t < 128) {
        float mu = g_sum[t] * (1.0f / NN);
        float var = g_sq[t] * (1.0f / NN) - mu * mu;
        float s = gamma[l * DH + t] * rsqrtf(var + BN_EPS);
        sc[t] = s;
        sh[t] = bbeta[l * DH + t] - mu * s;
    }
    __syncthreads();
    int i0 = blockIdx.x * 512 + t;
#pragma unroll
    for (int u = 0; u < 2; u++) {
        int i = i0 + u * 256;
        if (i >= NN * 32) return;
        int fb = (i & 31) << 2;
        float4 a = ((const float4*)g_a2)[i];
        uint2 hv = ((const uint2*)g_hh)[i];
        float2 h01 = unpack_half2(hv.x), h23 = unpack_half2(hv.y);
        float4 scv = *(float4*)&sc[fb];
        float4 shv = *(float4*)&sh[fb];
        float o0 = fmaxf(fmaf(a.x, scv.x, shv.x) + h01.x, 0.f);
        float o1 = fmaxf(fmaf(a.y, scv.y, shv.y) + h01.y, 0.f);
        float o2 = fmaxf(fmaf(a.z, scv.z, shv.z) + h23.x, 0.f);
        float o3 = fmaxf(fmaf(a.w, scv.w, shv.w) + h23.y, 0.f);
        ((uint2*)g_hh)[i] = make_uint2(pack_half2(o0, o1), pack_half2(o2, o3));
    }
}

// ---------------- output GEMM: out[N,40] = h @ W_out + b_out (h fp16) ----------------
__global__ void __launch_bounds__(256) k_out(const float* __restrict__ Wout,
                                             const float* __restrict__ bout,
                                             float* __restrict__ out) {
    __shared__ float Hs[32][132];
    __shared__ float Ws[DH * DOUT];
    __shared__ float Bs[DOUT];
    int tid = threadIdx.x;
    int m0 = blockIdx.x * 32;
    for (int j = tid; j < DH * DOUT; j += 256) Ws[j] = Wout[j];
    if (tid < DOUT) Bs[tid] = bout[tid];
#pragma unroll
    for (int j = 0; j < 4; j++) {
        int flat = tid + j * 256;
        int r = flat >> 5, c4 = flat & 31;
        int gr = m0 + r;
        float4 v = make_float4(0.f, 0.f, 0.f, 0.f);
        if (gr < NN) {
            uint2 u = ((const uint2*)g_hh)[(size_t)gr * 32 + c4];
            float2 f01 = unpack_half2(u.x), f23 = unpack_half2(u.y);
            v = make_float4(f01.x, f01.y, f23.x, f23.y);
        }
        *(float4*)&Hs[r][c4 << 2] = v;
    }
    __syncthreads();
    int r = tid >> 3;
    int cg = tid & 7;
    float acc[5] = {0.f, 0.f, 0.f, 0.f, 0.f};
    for (int k = 0; k < DH; k++) {
        float a = Hs[r][k];
#pragma unroll
        for (int j = 0; j < 5; j++) acc[j] += a * Ws[k * DOUT + cg * 5 + j];
    }
    int gr = m0 + r;
    if (gr < NN) {
#pragma unroll
        for (int j = 0; j < 5; j++)
            out[(size_t)gr * DOUT + cg * 5 + j] = acc[j] + Bs[cg * 5 + j];
    }
}

// ---------------- launch ----------------
extern "C" void kernel_launch(void* const* d_in, const int* in_sizes, int n_in,
                              void* d_out, int out_size) {
    const float* x     = (const float*)d_in[0];
    const float* ew    = (const float*)d_in[1];
    const float* W_in  = (const float*)d_in[2];
    const float* b_in  = (const float*)d_in[3];
    const float* convW = (const float*)d_in[4];
    const float* gamma = (const float*)d_in[5];
    const float* bbeta = (const float*)d_in[6];
    const float* W_out = (const float*)d_in[7];
    const float* b_out = (const float*)d_in[8];
    const int*   erow  = (const int*)d_in[9];
    const int*   ecol  = (const int*)d_in[10];
    float* out = (float*)d_out;

    float* p_a2;
    cudaGetSymbolAddress((void**)&p_a2, g_a2);

    cudaFuncSetAttribute(k_mma, cudaFuncAttributeMaxDynamicSharedMemorySize, SMEM_BYTES);
    cudaFuncSetAttribute(k_mma16, cudaFuncAttributeMaxDynamicSharedMemorySize, SMEM16);

    const int nchunks = (NN + 1023) / 1024;  // 98
    const int ngemm = (NN + 127) / 128;      // 782

    k_prep_bin<<<16, 256>>>(W_in);
    k_prep_b16<<<(NLAYERS * 4096 + 255) / 256, 256>>>(convW);
    k_splitx<<<(NN * 64 + 255) / 256, 256>>>(x);
    k_mma<<<ngemm, 256, SMEM_BYTES>>>(b_in);

    k_hist<<<(EE + 255) / 256, 256>>>(erow);
    k_scanA<<<nchunks, 1024>>>();
    k_scanBC<<<(NN + 255) / 256, 256>>>();
    k_scatter<<<(EE + 255) / 256, 256>>>(erow, ecol, ew);

    for (int l = 0; l < NLAYERS; l++) {
        k_spmm<<<(NN * 32 + 255) / 256, 256>>>();
        k_mma16<<<ngemm, 256, SMEM16>>>(l, p_a2);
        k_bnapply<<<(NN * 32 + 511) / 512, 256>>>(gamma, bbeta, l);
    }

    k_out<<<(NN + 31) / 32, 256>>>(W_out, b_out, out);
}